// round 3
// baseline (speedup 1.0000x reference)
#include <cuda_runtime.h>
#include <math.h>

#define B_   4
#define SEQ  2048
#define DM   256
#define NH   4
#define DH   64
#define DE   320      // 64 base + 256 TT dims
#define BHT  16       // B_*NH

// ---------------- scratch (device globals; no allocation) ----------------
__device__ float g_Qe[BHT * SEQ * DE];   // 40 MB  [bh][s][320]  (pre-scaled)
__device__ float g_Ke[BHT * SEQ * DE];   // 40 MB
__device__ float g_V [BHT * SEQ * DH];   // 8 MB   [bh][s][64]
__device__ float g_O [B_  * SEQ * DM];   // 8 MB   [b][s][256]  attn output

// =====================================================================
// Kernel 1: QKV projection GEMM.  z=0:Q  z=1:K  z=2:V
// out = X(8192x256) @ W(256x256) + b, scattered to (bh,s,d) layouts.
// 64x64 tile, 256 threads, 4x4 per thread, k-chunks of 16.
// =====================================================================
__global__ __launch_bounds__(256) void proj_kernel(
    const float* __restrict__ Xq, const float* __restrict__ Xk, const float* __restrict__ Xv,
    const float* __restrict__ Wq, const float* __restrict__ bq,
    const float* __restrict__ Wk, const float* __restrict__ bk,
    const float* __restrict__ Wv, const float* __restrict__ bv)
{
    __shared__ float As[64 * 17];
    __shared__ float Bs[16 * 68];
    const int z = blockIdx.z;
    const float* X    = (z == 0) ? Xq : (z == 1) ? Xk : Xv;
    const float* W    = (z == 0) ? Wq : (z == 1) ? Wk : Wv;
    const float* bias = (z == 0) ? bq : (z == 1) ? bk : bv;
    const int m0 = blockIdx.x * 64;
    const int n0 = blockIdx.y * 64;
    const int tid = threadIdx.x;
    const int tx = tid & 15, ty = tid >> 4;

    float acc[4][4] = {};
    for (int k0 = 0; k0 < DM; k0 += 16) {
        {
            int i = tid >> 2, c = tid & 3;
            float4 a = *(const float4*)&X[(size_t)(m0 + i) * DM + k0 + c * 4];
            As[i * 17 + c * 4 + 0] = a.x;
            As[i * 17 + c * 4 + 1] = a.y;
            As[i * 17 + c * 4 + 2] = a.z;
            As[i * 17 + c * 4 + 3] = a.w;
            int kk = tid >> 4, c2 = tid & 15;
            *(float4*)&Bs[kk * 68 + c2 * 4] =
                *(const float4*)&W[(size_t)(k0 + kk) * DM + n0 + c2 * 4];
        }
        __syncthreads();
        #pragma unroll
        for (int kk = 0; kk < 16; kk++) {
            float a0 = As[(ty * 4 + 0) * 17 + kk];
            float a1 = As[(ty * 4 + 1) * 17 + kk];
            float a2 = As[(ty * 4 + 2) * 17 + kk];
            float a3 = As[(ty * 4 + 3) * 17 + kk];
            float4 b = *(float4*)&Bs[kk * 68 + tx * 4];
            acc[0][0] += a0 * b.x; acc[0][1] += a0 * b.y; acc[0][2] += a0 * b.z; acc[0][3] += a0 * b.w;
            acc[1][0] += a1 * b.x; acc[1][1] += a1 * b.y; acc[1][2] += a1 * b.z; acc[1][3] += a1 * b.w;
            acc[2][0] += a2 * b.x; acc[2][1] += a2 * b.y; acc[2][2] += a2 * b.z; acc[2][3] += a2 * b.w;
            acc[3][0] += a3 * b.x; acc[3][1] += a3 * b.y; acc[3][2] += a3 * b.z; acc[3][3] += a3 * b.w;
        }
        __syncthreads();
    }

    const int h = n0 >> 6;            // 64-wide tiles align with heads
    #pragma unroll
    for (int ii = 0; ii < 4; ii++) {
        int m = m0 + ty * 4 + ii;
        int b = m >> 11, s = m & (SEQ - 1);
        float4 r;
        r.x = acc[ii][0] + bias[n0 + tx * 4 + 0];
        r.y = acc[ii][1] + bias[n0 + tx * 4 + 1];
        r.z = acc[ii][2] + bias[n0 + tx * 4 + 2];
        r.w = acc[ii][3] + bias[n0 + tx * 4 + 3];
        if (z == 0) {   // Q: pre-scale by 1/sqrt(Dh) = 0.125
            r.x *= 0.125f; r.y *= 0.125f; r.z *= 0.125f; r.w *= 0.125f;
            *(float4*)&g_Qe[(size_t)((b * NH + h) * SEQ + s) * DE + tx * 4] = r;
        } else if (z == 1) {
            *(float4*)&g_Ke[(size_t)((b * NH + h) * SEQ + s) * DE + tx * 4] = r;
        } else {
            *(float4*)&g_V [(size_t)((b * NH + h) * SEQ + s) * DH + tx * 4] = r;
        }
    }
}

// =====================================================================
// Kernel 2: TT projection.  var=0: Qp = Q @ W2[h,d,(a,r)]  (scaled alpha/512)
//                           var=1: Kp = K @ W2[h,a,(e),r]^T over e
// Writes the 256-dim tail of g_Qe / g_Ke.
// =====================================================================
#define TT_SMEM ((64 * 257 + 64 * 65) * 4)

__global__ __launch_bounds__(256) void tt_kernel(const float* __restrict__ W2,
                                                 const float* __restrict__ alpha_p)
{
    extern __shared__ float sm[];
    float* Ws = sm;              // 64 x 257
    float* Xs = sm + 64 * 257;   // 64 x 65
    const int var = blockIdx.z;
    const int bh  = blockIdx.y;
    const int h   = bh & 3;
    const int s0  = blockIdx.x * 64;
    const int tid = threadIdx.x;
    const float* W2h = W2 + (size_t)h * 64 * 256;   // W2[h,d,a,r] flat: d*256 + a*4 + r

    if (var == 0) {
        // Ws[d][c] = W2[h,d,a,r], c = a*4+r  (contiguous rows)
        for (int idx = tid; idx < 64 * 256; idx += 256)
            Ws[(idx >> 8) * 257 + (idx & 255)] = W2h[idx];
    } else {
        // Ws[e][c] = W2[h,a,e,r], c = a*4+r ; source idx = a*256 + e*4 + r
        for (int idx = tid; idx < 64 * 256; idx += 256) {
            int a = idx >> 8, rest = idx & 255;
            int e = rest >> 2, r = rest & 3;
            Ws[e * 257 + a * 4 + r] = W2h[idx];
        }
    }
    const float* src = (var == 0) ? g_Qe : g_Ke;
    const float xs   = (var == 0) ? 8.0f : 1.0f;   // undo Qe 1/8 pre-scale
    for (int idx = tid; idx < 64 * 64; idx += 256) {
        int i = idx >> 6, d = idx & 63;
        Xs[i * 65 + d] = src[(size_t)(bh * SEQ + s0 + i) * DE + d] * xs;
    }
    __syncthreads();

    const int tx = tid & 15, ty = tid >> 4;
    float acc[4][16] = {};
    for (int d = 0; d < 64; d++) {
        float x0 = Xs[(ty * 4 + 0) * 65 + d];
        float x1 = Xs[(ty * 4 + 1) * 65 + d];
        float x2 = Xs[(ty * 4 + 2) * 65 + d];
        float x3 = Xs[(ty * 4 + 3) * 65 + d];
        #pragma unroll
        for (int cc = 0; cc < 16; cc++) {
            float w = Ws[d * 257 + cc * 16 + tx];   // cyclic cols: conflict-free
            acc[0][cc] += x0 * w;
            acc[1][cc] += x1 * w;
            acc[2][cc] += x2 * w;
            acc[3][cc] += x3 * w;
        }
    }
    float* dst = (var == 0) ? g_Qe : g_Ke;
    const float osc = (var == 0) ? (alpha_p[0] * (1.0f / 512.0f)) : 1.0f; // alpha/(Dh*sqrt(Dh))
    #pragma unroll
    for (int ii = 0; ii < 4; ii++) {
        size_t base = (size_t)(bh * SEQ + s0 + ty * 4 + ii) * DE + 64;
        #pragma unroll
        for (int cc = 0; cc < 16; cc++)
            dst[base + cc * 16 + tx] = acc[ii][cc] * osc;
    }
}

// =====================================================================
// Kernel 3: flash attention, d_qk = 320, d_v = 64.
// Block: 64 q-rows x full k loop.  16x16 threads, 4x4 register tiles.
// Qe/Ke tiles XOR-swizzled in smem for conflict-light float4 reads.
// =====================================================================
#define ATTN_SMEM ((2 * 64 * 320 + 2 * 64 * 68) * 4)   // 198,656 B

__device__ __forceinline__ int swz(int row, int c4) {
    // row-major 64x320 tile, 16B chunks; chunk c4 in [0,80)
    int cs = (c4 & ~7) | ((c4 ^ (row >> 2)) & 7);
    return row * 320 + (cs << 2);
}

__global__ __launch_bounds__(256) void attn_kernel()
{
    extern __shared__ float sm[];
    float* Qs = sm;                       // 64*320 swizzled
    float* Ks = sm + 64 * 320;            // 64*320 swizzled
    float* Vs = sm + 2 * 64 * 320;        // 64*68
    float* Ps = Vs + 64 * 68;             // 64*68
    const int bh = blockIdx.y;
    const int qt = blockIdx.x;
    const int tid = threadIdx.x;
    const int tx = tid & 15, ty = tid >> 4;

    const float* Qg = g_Qe + (size_t)(bh * SEQ + qt * 64) * DE;
    #pragma unroll
    for (int it = 0; it < 20; it++) {
        int idx = tid + it * 256;
        int i = idx / 80, c = idx % 80;
        *(float4*)&Qs[swz(i, c)] = *(const float4*)&Qg[i * DE + c * 4];
    }

    float m_i[4], l_i[4], o[4][4];
    #pragma unroll
    for (int ii = 0; ii < 4; ii++) {
        m_i[ii] = -1e30f; l_i[ii] = 0.f;
        #pragma unroll
        for (int jj = 0; jj < 4; jj++) o[ii][jj] = 0.f;
    }
    __syncthreads();

    for (int kt = 0; kt < 32; kt++) {
        const float* Kg = g_Ke + (size_t)(bh * SEQ + kt * 64) * DE;
        #pragma unroll
        for (int it = 0; it < 20; it++) {
            int idx = tid + it * 256;
            int i = idx / 80, c = idx % 80;
            *(float4*)&Ks[swz(i, c)] = *(const float4*)&Kg[i * DE + c * 4];
        }
        const float* Vg = g_V + (size_t)(bh * SEQ + kt * 64) * DH;
        #pragma unroll
        for (int it = 0; it < 4; it++) {
            int idx = tid + it * 256;
            int k = idx >> 4, c = idx & 15;
            *(float4*)&Vs[k * 68 + c * 4] = *(const float4*)&Vg[k * DH + c * 4];
        }
        __syncthreads();

        // S tile = Qe(64x320) . Ke^T
        float s[4][4] = {};
        #pragma unroll 2
        for (int c4 = 0; c4 < 80; c4++) {
            float4 qf[4], kf[4];
            #pragma unroll
            for (int ii = 0; ii < 4; ii++) qf[ii] = *(float4*)&Qs[swz(ty * 4 + ii, c4)];
            #pragma unroll
            for (int jj = 0; jj < 4; jj++) kf[jj] = *(float4*)&Ks[swz(tx * 4 + jj, c4)];
            #pragma unroll
            for (int ii = 0; ii < 4; ii++)
                #pragma unroll
                for (int jj = 0; jj < 4; jj++) {
                    s[ii][jj] += qf[ii].x * kf[jj].x;
                    s[ii][jj] += qf[ii].y * kf[jj].y;
                    s[ii][jj] += qf[ii].z * kf[jj].z;
                    s[ii][jj] += qf[ii].w * kf[jj].w;
                }
        }

        // online softmax (rows grouped in 16-lane shuffle sets)
        #pragma unroll
        for (int ii = 0; ii < 4; ii++) {
            float r = fmaxf(fmaxf(s[ii][0], s[ii][1]), fmaxf(s[ii][2], s[ii][3]));
            r = fmaxf(r, __shfl_xor_sync(0xffffffffu, r, 1));
            r = fmaxf(r, __shfl_xor_sync(0xffffffffu, r, 2));
            r = fmaxf(r, __shfl_xor_sync(0xffffffffu, r, 4));
            r = fmaxf(r, __shfl_xor_sync(0xffffffffu, r, 8));
            float mn = fmaxf(m_i[ii], r);
            float corr = __expf(m_i[ii] - mn);
            m_i[ii] = mn;
            float rs = 0.f;
            #pragma unroll
            for (int jj = 0; jj < 4; jj++) {
                float p = __expf(s[ii][jj] - mn);
                s[ii][jj] = p;
                rs += p;
            }
            rs += __shfl_xor_sync(0xffffffffu, rs, 1);
            rs += __shfl_xor_sync(0xffffffffu, rs, 2);
            rs += __shfl_xor_sync(0xffffffffu, rs, 4);
            rs += __shfl_xor_sync(0xffffffffu, rs, 8);
            l_i[ii] = l_i[ii] * corr + rs;
            #pragma unroll
            for (int jj = 0; jj < 4; jj++) o[ii][jj] *= corr;
            *(float4*)&Ps[(ty * 4 + ii) * 68 + tx * 4] =
                make_float4(s[ii][0], s[ii][1], s[ii][2], s[ii][3]);
        }
        __syncthreads();

        // O += P(64x64) @ V(64x64)
        #pragma unroll 2
        for (int k = 0; k < 64; k += 4) {
            float4 vf[4];
            #pragma unroll
            for (int kk = 0; kk < 4; kk++) vf[kk] = *(float4*)&Vs[(k + kk) * 68 + tx * 4];
            #pragma unroll
            for (int ii = 0; ii < 4; ii++) {
                float4 pf = *(float4*)&Ps[(ty * 4 + ii) * 68 + k];
                o[ii][0] += pf.x * vf[0].x; o[ii][0] += pf.y * vf[1].x; o[ii][0] += pf.z * vf[2].x; o[ii][0] += pf.w * vf[3].x;
                o[ii][1] += pf.x * vf[0].y; o[ii][1] += pf.y * vf[1].y; o[ii][1] += pf.z * vf[2].y; o[ii][1] += pf.w * vf[3].y;
                o[ii][2] += pf.x * vf[0].z; o[ii][2] += pf.y * vf[1].z; o[ii][2] += pf.z * vf[2].z; o[ii][2] += pf.w * vf[3].z;
                o[ii][3] += pf.x * vf[0].w; o[ii][3] += pf.y * vf[1].w; o[ii][3] += pf.z * vf[2].w; o[ii][3] += pf.w * vf[3].w;
            }
        }
        __syncthreads();
    }

    const int b = bh >> 2, h = bh & 3;
    #pragma unroll
    for (int ii = 0; ii < 4; ii++) {
        float inv = 1.0f / l_i[ii];
        int srow = qt * 64 + ty * 4 + ii;
        *(float4*)&g_O[(size_t)(b * SEQ + srow) * DM + h * 64 + tx * 4] =
            make_float4(o[ii][0] * inv, o[ii][1] * inv, o[ii][2] * inv, o[ii][3] * inv);
    }
}

// =====================================================================
// Kernel 4: output projection  d_out = g_O(8192x256) @ Wo + bo
// =====================================================================
__global__ __launch_bounds__(256) void out_kernel(const float* __restrict__ Wo,
                                                  const float* __restrict__ bo,
                                                  float* __restrict__ out)
{
    __shared__ float As[64 * 17];
    __shared__ float Bs[16 * 68];
    const int m0 = blockIdx.x * 64;
    const int n0 = blockIdx.y * 64;
    const int tid = threadIdx.x;
    const int tx = tid & 15, ty = tid >> 4;

    float acc[4][4] = {};
    for (int k0 = 0; k0 < DM; k0 += 16) {
        {
            int i = tid >> 2, c = tid & 3;
            float4 a = *(const float4*)&g_O[(size_t)(m0 + i) * DM + k0 + c * 4];
            As[i * 17 + c * 4 + 0] = a.x;
            As[i * 17 + c * 4 + 1] = a.y;
            As[i * 17 + c * 4 + 2] = a.z;
            As[i * 17 + c * 4 + 3] = a.w;
            int kk = tid >> 4, c2 = tid & 15;
            *(float4*)&Bs[kk * 68 + c2 * 4] =
                *(const float4*)&Wo[(size_t)(k0 + kk) * DM + n0 + c2 * 4];
        }
        __syncthreads();
        #pragma unroll
        for (int kk = 0; kk < 16; kk++) {
            float a0 = As[(ty * 4 + 0) * 17 + kk];
            float a1 = As[(ty * 4 + 1) * 17 + kk];
            float a2 = As[(ty * 4 + 2) * 17 + kk];
            float a3 = As[(ty * 4 + 3) * 17 + kk];
            float4 b = *(float4*)&Bs[kk * 68 + tx * 4];
            acc[0][0] += a0 * b.x; acc[0][1] += a0 * b.y; acc[0][2] += a0 * b.z; acc[0][3] += a0 * b.w;
            acc[1][0] += a1 * b.x; acc[1][1] += a1 * b.y; acc[1][2] += a1 * b.z; acc[1][3] += a1 * b.w;
            acc[2][0] += a2 * b.x; acc[2][1] += a2 * b.y; acc[2][2] += a2 * b.z; acc[2][3] += a2 * b.w;
            acc[3][0] += a3 * b.x; acc[3][1] += a3 * b.y; acc[3][2] += a3 * b.z; acc[3][3] += a3 * b.w;
        }
        __syncthreads();
    }

    #pragma unroll
    for (int ii = 0; ii < 4; ii++) {
        int m = m0 + ty * 4 + ii;
        float4 r;
        r.x = acc[ii][0] + bo[n0 + tx * 4 + 0];
        r.y = acc[ii][1] + bo[n0 + tx * 4 + 1];
        r.z = acc[ii][2] + bo[n0 + tx * 4 + 2];
        r.w = acc[ii][3] + bo[n0 + tx * 4 + 3];
        *(float4*)&out[(size_t)m * DM + n0 + tx * 4] = r;
    }
}

// =====================================================================
extern "C" void kernel_launch(void* const* d_in, const int* in_sizes, int n_in,
                              void* d_out, int out_size)
{
    const float* query = (const float*)d_in[0];
    const float* key_  = (const float*)d_in[1];
    const float* value = (const float*)d_in[2];
    const float* Wq    = (const float*)d_in[3];
    const float* bq    = (const float*)d_in[4];
    const float* Wk    = (const float*)d_in[5];
    const float* bk    = (const float*)d_in[6];
    const float* Wv    = (const float*)d_in[7];
    const float* bv    = (const float*)d_in[8];
    const float* W2    = (const float*)d_in[9];
    const float* alpha = (const float*)d_in[10];
    const float* Wo    = (const float*)d_in[11];
    const float* bo    = (const float*)d_in[12];
    float* out = (float*)d_out;

    cudaFuncSetAttribute(tt_kernel,   cudaFuncAttributeMaxDynamicSharedMemorySize, TT_SMEM);
    cudaFuncSetAttribute(attn_kernel, cudaFuncAttributeMaxDynamicSharedMemorySize, ATTN_SMEM);

    // 1. QKV projections -> Qe base (pre-scaled), Ke base, V
    proj_kernel<<<dim3(128, 4, 3), 256>>>(query, key_, value, Wq, bq, Wk, bk, Wv, bv);
    // 2. TT projections -> Qe/Ke 256-dim tails
    tt_kernel<<<dim3(32, BHT, 2), 256, TT_SMEM>>>(W2, alpha);
    // 3. flash attention (d_qk=320, d_v=64) -> g_O
    attn_kernel<<<dim3(32, BHT), 256, ATTN_SMEM>>>();
    // 4. output projection -> d_out
    out_kernel<<<dim3(128, 4), 256>>>(Wo, bo, out);
}

// round 4
// speedup vs baseline: 3.4843x; 3.4843x over previous
#include <cuda_runtime.h>
#include <math.h>

#define B_   4
#define SEQ  2048
#define DM   256
#define NH   4
#define DH   64
#define BHT  16       // B_*NH

// ---------------- scratch (device globals; no allocation) ----------------
__device__ float g_Q [BHT * SEQ * DH];   // 8 MB  [bh][s][64]  (pre-scaled by 1/8)
__device__ float g_K [BHT * SEQ * DH];   // 8 MB  effective K = K·G^T
__device__ float g_V [BHT * SEQ * DH];   // 8 MB
__device__ float g_O [B_  * SEQ * DM];   // 8 MB  attn output
__device__ float g_Wk[DM * DM];          // folded Wk_eff
__device__ float g_bk[DM];               // folded bk_eff

// =====================================================================
// Kernel 0: prep — fold TT interaction into Wk.
//   M_h[d,e] = sum_{a,r} W2[h,d,a,r] * W2[h,a,e,r]
//   G_h      = I + (alpha/64) * M_h
//   Wk_eff[:, h*64+d] = sum_e Wk[:, h*64+e] * G_h[d,e];  bk_eff likewise.
// One block per head, 256 threads.
// =====================================================================
#define PREP_SMEM ((64 * 256 + 64 * 65) * 4)

__global__ __launch_bounds__(256) void prep_kernel(const float* __restrict__ W2,
                                                   const float* __restrict__ alpha_p,
                                                   const float* __restrict__ Wk,
                                                   const float* __restrict__ bk)
{
    extern __shared__ float sm[];
    float* Ws = sm;              // W2_h : [d][a*4+r]  (64 x 256)
    float* Gs = sm + 64 * 256;   // G    : [d][e]      (64 x 65 padded)
    const int h = blockIdx.x;
    const int tid = threadIdx.x;
    const float* W2h = W2 + (size_t)h * 64 * 256;

    for (int idx = tid; idx < 64 * 256; idx += 256) Ws[idx] = W2h[idx];
    __syncthreads();

    const float c = alpha_p[0] * (1.0f / 64.0f);
    for (int idx = tid; idx < 64 * 64; idx += 256) {
        int d = idx >> 6, e = idx & 63;
        float s = 0.f;
        #pragma unroll 8
        for (int a = 0; a < 64; a++) {
            float4 wa = *(const float4*)&Ws[d * 256 + a * 4];
            float4 wb = *(const float4*)&Ws[a * 256 + e * 4];
            s += wa.x * wb.x + wa.y * wb.y + wa.z * wb.z + wa.w * wb.w;
        }
        Gs[d * 65 + e] = c * s + ((d == e) ? 1.0f : 0.0f);
    }
    __syncthreads();

    // Wk_eff rows: thread tid owns input row c_row
    {
        const int cr = tid;
        float kin[64];
        #pragma unroll
        for (int e = 0; e < 64; e++) kin[e] = Wk[(size_t)cr * DM + h * 64 + e];
        for (int d = 0; d < 64; d++) {
            float s = 0.f;
            #pragma unroll
            for (int e = 0; e < 64; e++) s += kin[e] * Gs[d * 65 + e];
            g_Wk[(size_t)cr * DM + h * 64 + d] = s;
        }
    }
    if (tid < 64) {
        int d = tid;
        float s = 0.f;
        #pragma unroll
        for (int e = 0; e < 64; e++) s += bk[h * 64 + e] * Gs[d * 65 + e];
        g_bk[h * 64 + d] = s;
    }
}

// =====================================================================
// Kernel 1: QKV projection GEMM.  z=0:Q (x0.125)  z=1:K (uses folded Wk)  z=2:V
// 64x64 tile, 256 threads, 4x4 per thread.
// =====================================================================
__global__ __launch_bounds__(256) void proj_kernel(
    const float* __restrict__ Xq, const float* __restrict__ Xk, const float* __restrict__ Xv,
    const float* __restrict__ Wq, const float* __restrict__ bq,
    const float* __restrict__ Wv, const float* __restrict__ bv)
{
    __shared__ float As[64 * 17];
    __shared__ float Bs[16 * 68];
    const int z = blockIdx.z;
    const float* X    = (z == 0) ? Xq : (z == 1) ? Xk : Xv;
    const float* W    = (z == 0) ? Wq : (z == 1) ? g_Wk : Wv;
    const float* bias = (z == 0) ? bq : (z == 1) ? g_bk : bv;
    const int m0 = blockIdx.x * 64;
    const int n0 = blockIdx.y * 64;
    const int tid = threadIdx.x;
    const int tx = tid & 15, ty = tid >> 4;

    float acc[4][4] = {};
    for (int k0 = 0; k0 < DM; k0 += 16) {
        {
            int i = tid >> 2, c = tid & 3;
            float4 a = *(const float4*)&X[(size_t)(m0 + i) * DM + k0 + c * 4];
            As[i * 17 + c * 4 + 0] = a.x;
            As[i * 17 + c * 4 + 1] = a.y;
            As[i * 17 + c * 4 + 2] = a.z;
            As[i * 17 + c * 4 + 3] = a.w;
            int kk = tid >> 4, c2 = tid & 15;
            *(float4*)&Bs[kk * 68 + c2 * 4] =
                *(const float4*)&W[(size_t)(k0 + kk) * DM + n0 + c2 * 4];
        }
        __syncthreads();
        #pragma unroll
        for (int kk = 0; kk < 16; kk++) {
            float a0 = As[(ty * 4 + 0) * 17 + kk];
            float a1 = As[(ty * 4 + 1) * 17 + kk];
            float a2 = As[(ty * 4 + 2) * 17 + kk];
            float a3 = As[(ty * 4 + 3) * 17 + kk];
            float4 b = *(float4*)&Bs[kk * 68 + tx * 4];
            acc[0][0] += a0 * b.x; acc[0][1] += a0 * b.y; acc[0][2] += a0 * b.z; acc[0][3] += a0 * b.w;
            acc[1][0] += a1 * b.x; acc[1][1] += a1 * b.y; acc[1][2] += a1 * b.z; acc[1][3] += a1 * b.w;
            acc[2][0] += a2 * b.x; acc[2][1] += a2 * b.y; acc[2][2] += a2 * b.z; acc[2][3] += a2 * b.w;
            acc[3][0] += a3 * b.x; acc[3][1] += a3 * b.y; acc[3][2] += a3 * b.z; acc[3][3] += a3 * b.w;
        }
        __syncthreads();
    }

    const int h = n0 >> 6;
    float* dst = (z == 0) ? g_Q : (z == 1) ? g_K : g_V;
    const float sc = (z == 0) ? 0.125f : 1.0f;
    #pragma unroll
    for (int ii = 0; ii < 4; ii++) {
        int m = m0 + ty * 4 + ii;
        int b = m >> 11, s = m & (SEQ - 1);
        float4 r;
        r.x = (acc[ii][0] + bias[n0 + tx * 4 + 0]) * sc;
        r.y = (acc[ii][1] + bias[n0 + tx * 4 + 1]) * sc;
        r.z = (acc[ii][2] + bias[n0 + tx * 4 + 2]) * sc;
        r.w = (acc[ii][3] + bias[n0 + tx * 4 + 3]) * sc;
        *(float4*)&dst[(size_t)((b * NH + h) * SEQ + s) * DH + tx * 4] = r;
    }
}

// =====================================================================
// Kernel 2: flash attention, d_qk = d_v = 64.
// Block: 64 q-rows, loop over 32 k-tiles of 64.  16x16 threads, 4x4 tiles.
// Q/K tiles XOR-swizzled; 68 KB smem -> 2 blocks/SM.
// =====================================================================
#define ATTN_SMEM ((2 * 64 * 64 + 2 * 64 * 68) * 4)   // 67,584 B

__device__ __forceinline__ int swz64(int row, int c4) {
    // row-major 64x64 tile, 16B chunks; c4 in [0,16)
    int cs = (c4 & 8) | ((c4 ^ (row >> 2)) & 7);
    return row * 64 + (cs << 2);
}

__global__ __launch_bounds__(256, 2) void attn_kernel()
{
    extern __shared__ float sm[];
    float* Qs = sm;                       // 64*64 swizzled
    float* Ks = sm + 64 * 64;             // 64*64 swizzled
    float* Vs = sm + 2 * 64 * 64;         // 64*68
    float* Ps = Vs + 64 * 68;             // 64*68
    const int bh = blockIdx.y;
    const int qt = blockIdx.x;
    const int tid = threadIdx.x;
    const int tx = tid & 15, ty = tid >> 4;

    const float* Qg = g_Q + (size_t)(bh * SEQ + qt * 64) * DH;
    #pragma unroll
    for (int it = 0; it < 4; it++) {
        int idx = tid + it * 256;
        int i = idx >> 4, c = idx & 15;
        *(float4*)&Qs[swz64(i, c)] = *(const float4*)&Qg[i * DH + c * 4];
    }

    float m_i[4], l_i[4], o[4][4];
    #pragma unroll
    for (int ii = 0; ii < 4; ii++) {
        m_i[ii] = -1e30f; l_i[ii] = 0.f;
        #pragma unroll
        for (int jj = 0; jj < 4; jj++) o[ii][jj] = 0.f;
    }
    __syncthreads();

    for (int kt = 0; kt < 32; kt++) {
        const float* Kg = g_K + (size_t)(bh * SEQ + kt * 64) * DH;
        const float* Vg = g_V + (size_t)(bh * SEQ + kt * 64) * DH;
        #pragma unroll
        for (int it = 0; it < 4; it++) {
            int idx = tid + it * 256;
            int i = idx >> 4, c = idx & 15;
            *(float4*)&Ks[swz64(i, c)] = *(const float4*)&Kg[i * DH + c * 4];
            *(float4*)&Vs[i * 68 + c * 4] = *(const float4*)&Vg[i * DH + c * 4];
        }
        __syncthreads();

        // S tile = Q(64x64) . K^T
        float s[4][4] = {};
        #pragma unroll 4
        for (int c4 = 0; c4 < 16; c4++) {
            float4 qf[4], kf[4];
            #pragma unroll
            for (int ii = 0; ii < 4; ii++) qf[ii] = *(float4*)&Qs[swz64(ty * 4 + ii, c4)];
            #pragma unroll
            for (int jj = 0; jj < 4; jj++) kf[jj] = *(float4*)&Ks[swz64(tx * 4 + jj, c4)];
            #pragma unroll
            for (int ii = 0; ii < 4; ii++)
                #pragma unroll
                for (int jj = 0; jj < 4; jj++) {
                    s[ii][jj] += qf[ii].x * kf[jj].x;
                    s[ii][jj] += qf[ii].y * kf[jj].y;
                    s[ii][jj] += qf[ii].z * kf[jj].z;
                    s[ii][jj] += qf[ii].w * kf[jj].w;
                }
        }

        // online softmax (rows reduced across 16 lanes)
        #pragma unroll
        for (int ii = 0; ii < 4; ii++) {
            float r = fmaxf(fmaxf(s[ii][0], s[ii][1]), fmaxf(s[ii][2], s[ii][3]));
            r = fmaxf(r, __shfl_xor_sync(0xffffffffu, r, 1));
            r = fmaxf(r, __shfl_xor_sync(0xffffffffu, r, 2));
            r = fmaxf(r, __shfl_xor_sync(0xffffffffu, r, 4));
            r = fmaxf(r, __shfl_xor_sync(0xffffffffu, r, 8));
            float mn = fmaxf(m_i[ii], r);
            float corr = __expf(m_i[ii] - mn);
            m_i[ii] = mn;
            float rs = 0.f;
            #pragma unroll
            for (int jj = 0; jj < 4; jj++) {
                float p = __expf(s[ii][jj] - mn);
                s[ii][jj] = p;
                rs += p;
            }
            rs += __shfl_xor_sync(0xffffffffu, rs, 1);
            rs += __shfl_xor_sync(0xffffffffu, rs, 2);
            rs += __shfl_xor_sync(0xffffffffu, rs, 4);
            rs += __shfl_xor_sync(0xffffffffu, rs, 8);
            l_i[ii] = l_i[ii] * corr + rs;
            #pragma unroll
            for (int jj = 0; jj < 4; jj++) o[ii][jj] *= corr;
            *(float4*)&Ps[(ty * 4 + ii) * 68 + tx * 4] =
                make_float4(s[ii][0], s[ii][1], s[ii][2], s[ii][3]);
        }
        __syncthreads();

        // O += P(64x64) @ V(64x64)
        #pragma unroll 4
        for (int k = 0; k < 64; k += 4) {
            float4 vf[4];
            #pragma unroll
            for (int kk = 0; kk < 4; kk++) vf[kk] = *(float4*)&Vs[(k + kk) * 68 + tx * 4];
            #pragma unroll
            for (int ii = 0; ii < 4; ii++) {
                float4 pf = *(float4*)&Ps[(ty * 4 + ii) * 68 + k];
                o[ii][0] += pf.x * vf[0].x; o[ii][0] += pf.y * vf[1].x; o[ii][0] += pf.z * vf[2].x; o[ii][0] += pf.w * vf[3].x;
                o[ii][1] += pf.x * vf[0].y; o[ii][1] += pf.y * vf[1].y; o[ii][1] += pf.z * vf[2].y; o[ii][1] += pf.w * vf[3].y;
                o[ii][2] += pf.x * vf[0].z; o[ii][2] += pf.y * vf[1].z; o[ii][2] += pf.z * vf[2].z; o[ii][2] += pf.w * vf[3].z;
                o[ii][3] += pf.x * vf[0].w; o[ii][3] += pf.y * vf[1].w; o[ii][3] += pf.z * vf[2].w; o[ii][3] += pf.w * vf[3].w;
            }
        }
        __syncthreads();
    }

    const int b = bh >> 2, h = bh & 3;
    #pragma unroll
    for (int ii = 0; ii < 4; ii++) {
        float inv = 1.0f / l_i[ii];
        int srow = qt * 64 + ty * 4 + ii;
        *(float4*)&g_O[(size_t)(b * SEQ + srow) * DM + h * 64 + tx * 4] =
            make_float4(o[ii][0] * inv, o[ii][1] * inv, o[ii][2] * inv, o[ii][3] * inv);
    }
}

// =====================================================================
// Kernel 3: output projection  d_out = g_O(8192x256) @ Wo + bo
// =====================================================================
__global__ __launch_bounds__(256) void out_kernel(const float* __restrict__ Wo,
                                                  const float* __restrict__ bo,
                                                  float* __restrict__ out)
{
    __shared__ float As[64 * 17];
    __shared__ float Bs[16 * 68];
    const int m0 = blockIdx.x * 64;
    const int n0 = blockIdx.y * 64;
    const int tid = threadIdx.x;
    const int tx = tid & 15, ty = tid >> 4;

    float acc[4][4] = {};
    for (int k0 = 0; k0 < DM; k0 += 16) {
        {
            int i = tid >> 2, c = tid & 3;
            float4 a = *(const float4*)&g_O[(size_t)(m0 + i) * DM + k0 + c * 4];
            As[i * 17 + c * 4 + 0] = a.x;
            As[i * 17 + c * 4 + 1] = a.y;
            As[i * 17 + c * 4 + 2] = a.z;
            As[i * 17 + c * 4 + 3] = a.w;
            int kk = tid >> 4, c2 = tid & 15;
            *(float4*)&Bs[kk * 68 + c2 * 4] =
                *(const float4*)&Wo[(size_t)(k0 + kk) * DM + n0 + c2 * 4];
        }
        __syncthreads();
        #pragma unroll
        for (int kk = 0; kk < 16; kk++) {
            float a0 = As[(ty * 4 + 0) * 17 + kk];
            float a1 = As[(ty * 4 + 1) * 17 + kk];
            float a2 = As[(ty * 4 + 2) * 17 + kk];
            float a3 = As[(ty * 4 + 3) * 17 + kk];
            float4 b = *(float4*)&Bs[kk * 68 + tx * 4];
            acc[0][0] += a0 * b.x; acc[0][1] += a0 * b.y; acc[0][2] += a0 * b.z; acc[0][3] += a0 * b.w;
            acc[1][0] += a1 * b.x; acc[1][1] += a1 * b.y; acc[1][2] += a1 * b.z; acc[1][3] += a1 * b.w;
            acc[2][0] += a2 * b.x; acc[2][1] += a2 * b.y; acc[2][2] += a2 * b.z; acc[2][3] += a2 * b.w;
            acc[3][0] += a3 * b.x; acc[3][1] += a3 * b.y; acc[3][2] += a3 * b.z; acc[3][3] += a3 * b.w;
        }
        __syncthreads();
    }

    #pragma unroll
    for (int ii = 0; ii < 4; ii++) {
        int m = m0 + ty * 4 + ii;
        float4 r;
        r.x = acc[ii][0] + bo[n0 + tx * 4 + 0];
        r.y = acc[ii][1] + bo[n0 + tx * 4 + 1];
        r.z = acc[ii][2] + bo[n0 + tx * 4 + 2];
        r.w = acc[ii][3] + bo[n0 + tx * 4 + 3];
        *(float4*)&out[(size_t)m * DM + n0 + tx * 4] = r;
    }
}

// =====================================================================
extern "C" void kernel_launch(void* const* d_in, const int* in_sizes, int n_in,
                              void* d_out, int out_size)
{
    const float* query = (const float*)d_in[0];
    const float* key_  = (const float*)d_in[1];
    const float* value = (const float*)d_in[2];
    const float* Wq    = (const float*)d_in[3];
    const float* bq    = (const float*)d_in[4];
    const float* Wk    = (const float*)d_in[5];
    const float* bk    = (const float*)d_in[6];
    const float* Wv    = (const float*)d_in[7];
    const float* bv    = (const float*)d_in[8];
    const float* W2    = (const float*)d_in[9];
    const float* alpha = (const float*)d_in[10];
    const float* Wo    = (const float*)d_in[11];
    const float* bo    = (const float*)d_in[12];
    float* out = (float*)d_out;

    cudaFuncSetAttribute(prep_kernel, cudaFuncAttributeMaxDynamicSharedMemorySize, PREP_SMEM);
    cudaFuncSetAttribute(attn_kernel, cudaFuncAttributeMaxDynamicSharedMemorySize, ATTN_SMEM);

    // 0. fold TT interaction into Wk/bk  (G_h = I + (alpha/64) M_h)
    prep_kernel<<<NH, 256, PREP_SMEM>>>(W2, alpha, Wk, bk);
    // 1. QKV projections (K uses folded weights)
    proj_kernel<<<dim3(128, 4, 3), 256>>>(query, key_, value, Wq, bq, Wv, bv);
    // 2. flash attention (d=64) -> g_O
    attn_kernel<<<dim3(32, BHT), 256, ATTN_SMEM>>>();
    // 3. output projection -> d_out
    out_kernel<<<dim3(128, 4), 256>>>(Wo, bo, out);
}